// round 12
// baseline (speedup 1.0000x reference)
#include <cuda_runtime.h>
#include <cuda_fp16.h>
#include <cstdint>

#define N_EDGES   400000
#define TE        128
#define NBLK      (N_EDGES / TE)   // 3125, exact
#define WN        576
#define C3F       0.5773502691896257f
#define S0F       0.006378879538497861f   // sqrt(1/24)/32
#define SILU_NORM 1.6791767923989418f

typedef uint32_t u32;

// ---- weight fragment tables (fp16, mma.sync fragment order) ----------------
__device__ u32 g_B2[9][4][8][32][2];
__device__ u32 g_B1[4][8][32][2];

__device__ __forceinline__ int w2col(int mp) {
  int j = mp & 15, gr = mp >> 4, g = gr >> 2, r = gr & 3;
  if (g < 4) return j * 16 + r + 4 * g;
  if (g < 6) return 448 + (j & 7) * 16 + r + 4 * ((g - 4) * 2 + (j >> 3));
  if (g < 8) return 256 + j * 8 + 2 * r + (g - 6);
  return 384 + (j & 7) * 8 + 2 * r + (j >> 3);
}

__device__ __forceinline__ void split_pack_h(float v0, float v1, u32 &hi, u32 &lo) {
  __half h0 = __float2half_rn(v0), h1 = __float2half_rn(v1);
  __half l0 = __float2half_rn(v0 - __half2float(h0));
  __half l1 = __float2half_rn(v1 - __half2float(h1));
  __half2 H; H.x = h0; H.y = h1;
  __half2 L; L.x = l0; L.y = l1;
  hi = *(u32*)&H;  lo = *(u32*)&L;
}
__device__ __forceinline__ u32 pack_h(float v0, float v1) {
  __half2 H; H.x = __float2half_rn(v0); H.y = __float2half_rn(v1);
  return *(u32*)&H;
}

__global__ void prep_frags(const float* __restrict__ W1,
                           const float* __restrict__ W2) {
  int idx = blockIdx.x * blockDim.x + threadIdx.x;
  if (idx >= 10240) return;
  int lane = idx & 31;
  int nt = (idx >> 5) & 7;
  int kt = (idx >> 8) & 3;
  int C  = idx >> 10;                 // 0..8 = W2 chunks, 9 = W1
  int g = lane >> 2, c = lane & 3;
  int n = nt * 8 + g;
  #pragma unroll
  for (int r = 0; r < 2; r++) {
    int k = kt * 16 + c * 2 + r * 8;
    float v0, v1;
    if (C < 9) {
      int m = w2col(C * 64 + n);
      v0 = W2[k * WN + m];  v1 = W2[(k + 1) * WN + m];
    } else {
      v0 = W1[k * 64 + n];  v1 = W1[(k + 1) * 64 + n];
    }
    u32 hv = pack_h(v0, v1);
    if (C < 9) g_B2[C][kt][nt][lane][r] = hv;
    else       g_B1[kt][nt][lane][r]    = hv;
  }
}

__device__ __forceinline__ void mma16816h(float (&d)[4], const u32 (&a)[4],
                                          const u32 (&b)[2]) {
  asm volatile(
      "mma.sync.aligned.m16n8k16.row.col.f32.f16.f16.f32 "
      "{%0,%1,%2,%3}, {%4,%5,%6,%7}, {%8,%9}, {%0,%1,%2,%3};"
      : "+f"(d[0]), "+f"(d[1]), "+f"(d[2]), "+f"(d[3])
      : "r"(a[0]), "r"(a[1]), "r"(a[2]), "r"(a[3]), "r"(b[0]), "r"(b[1]));
}

#define SMEM_BYTES 16384   // two 8KB fp16 B buffers

__device__ __forceinline__ void stage(int t, u32* dst, const u32* src) {
  #pragma unroll
  for (int i = 0; i < 2; i++)
    ((uint4*)dst)[t + i * 256] = ((const uint4*)src)[t + i * 256];
}

// ---- fragment-side epilogue for one half (nt = 4h..4h+3), 2 row-slots ------
template <int G>
__device__ __forceinline__ void epi_half(
    int h, int c, const float (&acc)[4][4],
    const float (&x0v)[2][4], const float (&y0v)[2],
    const float (&z4v)[2][2], const float (&y1v)[2][3], const float (&x1v)[2][6],
    float (&oA)[2][4], float (&oB)[2][2][3])
{
  if (G < 4 || G == 6 || G == 7) {            // x0-dot classes (w1, w2)
    float P[2][2] = {};
    #pragma unroll
    for (int q = 0; q < 4; q++) {
      const int rrl = q >> 1, js = (q & 1) * 2;
      P[0][rrl] += acc[q][0]*x0v[0][js] + acc[q][1]*x0v[0][js+1];
      P[1][rrl] += acc[q][2]*x0v[1][js] + acc[q][3]*x0v[1][js+1];
    }
    #pragma unroll
    for (int rrl = 0; rrl < 2; rrl++)
      #pragma unroll
      for (int slot = 0; slot < 2; slot++) {
        float v = P[slot][rrl];
        v += __shfl_xor_sync(0xffffffffu, v, 1);
        v += __shfl_xor_sync(0xffffffffu, v, 2);
        if (c == 2*h + rrl) {
          if (G < 4) {
            oA[slot][G] += y0v[slot] * v;
          } else {
            oB[slot][G-6][0] += v * y1v[slot][0];
            oB[slot][G-6][1] += v * y1v[slot][1];
            oB[slot][G-6][2] += v * y1v[slot][2];
          }
        }
      }
  } else if (G < 6) {                          // w4: z4-dot, sA/sB per rr
    float P[2][2][2] = {};
    #pragma unroll
    for (int q = 0; q < 4; q++) {
      const int rrl = q >> 1, sel = q & 1;
      P[0][rrl][sel] += acc[q][0]*z4v[0][0] + acc[q][1]*z4v[0][1];
      P[1][rrl][sel] += acc[q][2]*z4v[1][0] + acc[q][3]*z4v[1][1];
    }
    #pragma unroll
    for (int rrl = 0; rrl < 2; rrl++)
      #pragma unroll
      for (int slot = 0; slot < 2; slot++)
        #pragma unroll
        for (int sel = 0; sel < 2; sel++) {
          float v = P[slot][rrl][sel];
          v += __shfl_xor_sync(0xffffffffu, v, 1);
          v += __shfl_xor_sync(0xffffffffu, v, 2);
          if (c == 2*h + rrl) oA[slot][2*(G-4)+sel] += C3F * v;
        }
  } else {                                     // G == 8, w3: x1-weighted
    #pragma unroll
    for (int q = 0; q < 4; q++) {
      const int rrl = q >> 1, hf = q & 1;
      float S[2][3] = {};
      #pragma unroll
      for (int i = 0; i < 3; i++) {
        S[0][i] += acc[q][0]*x1v[0][i] + acc[q][1]*x1v[0][3+i];
        S[1][i] += acc[q][2]*x1v[1][i] + acc[q][3]*x1v[1][3+i];
      }
      #pragma unroll
      for (int slot = 0; slot < 2; slot++)
        #pragma unroll
        for (int i = 0; i < 3; i++) {
          float v = S[slot][i];
          v += __shfl_xor_sync(0xffffffffu, v, 1);
          v += __shfl_xor_sync(0xffffffffu, v, 2);
          if (c == 2*h + rrl) oB[slot][hf][i] += y0v[slot] * v;
        }
    }
  }
}

// ---- one GEMM2 chunk: MMA (both halves) + fragment epilogue ----------------
template <int G>
__device__ __forceinline__ void chunk_proc(
    int lane, int c, const u32* __restrict__ bcur,
    const u32 (&A2h)[4][4], const u32 (&A2l)[4][4],
    const float (&x0v)[2][4], const float (&y0v)[2],
    const int (&rowE)[2], const int (&dstE)[2],
    const float* __restrict__ node_input, const float* __restrict__ edge_attr,
    float (&oA)[2][4], float (&oB)[2][2][3])
{
  float z4v[2][2];  float y1v[2][3];  float x1v[2][6];
  if (G == 4 || G == 5) {
    #pragma unroll
    for (int slot = 0; slot < 2; slot++) {
      float4 ya = ((const float4*)edge_attr)[rowE[slot]];
      const float* xp = node_input + (long)dstE[slot] * 40 + 16 + 6 * c;
      z4v[slot][0] = xp[0]*ya.y + xp[1]*ya.z + xp[2]*ya.w;
      z4v[slot][1] = xp[3]*ya.y + xp[4]*ya.z + xp[5]*ya.w;
    }
  }
  if (G == 6 || G == 7) {
    #pragma unroll
    for (int slot = 0; slot < 2; slot++) {
      float4 ya = ((const float4*)edge_attr)[rowE[slot]];
      y1v[slot][0] = ya.y;  y1v[slot][1] = ya.z;  y1v[slot][2] = ya.w;
    }
  }
  if (G == 8) {
    #pragma unroll
    for (int slot = 0; slot < 2; slot++) {
      const float* xp = node_input + (long)dstE[slot] * 40 + 16 + 6 * c;
      #pragma unroll
      for (int i = 0; i < 6; i++) x1v[slot][i] = xp[i];
    }
  }

  #pragma unroll
  for (int h = 0; h < 2; h++) {
    float acc[4][4];
    #pragma unroll
    for (int q = 0; q < 4; q++)
      #pragma unroll
      for (int i = 0; i < 4; i++) acc[q][i] = 0.f;

    #pragma unroll
    for (int kt = 0; kt < 4; kt++)
      #pragma unroll
      for (int q = 0; q < 4; q++) {
        const int nt = 4 * h + q;
        u32 b[2];
        *(uint2*)b = *(const uint2*)&bcur[((kt * 8 + nt) * 32 + lane) * 2];
        mma16816h(acc[q], A2h[kt], b);
        mma16816h(acc[q], A2l[kt], b);
      }
    epi_half<G>(h, c, acc, x0v, y0v, z4v, y1v, x1v, oA, oB);
  }
}

// ---- main kernel ------------------------------------------------------------
__global__ __launch_bounds__(256, 2) void fused_conv(
    const float* __restrict__ node_input,
    const int*   __restrict__ edge_src,
    const int*   __restrict__ edge_dst,
    const float* __restrict__ edge_attr,
    const float* __restrict__ dist,
    float* __restrict__ out)
{
  extern __shared__ u32 smu[];
  u32* sB0 = smu;
  u32* sB1 = smu + 2048;

  const int t = threadIdx.x;
  const int lane = t & 31, w = t >> 5;     // 8 warps, 16 rows each
  const int g = lane >> 2, c = lane & 3;
  const int e0 = blockIdx.x * TE;

  // per-lane row metadata (2 rows: slot s -> row 16w + 8s + g)
  int rowE[2], dstE[2];
  float y0v[2];
  #pragma unroll
  for (int slot = 0; slot < 2; slot++) {
    rowE[slot] = e0 + 16 * w + 8 * slot + g;
    dstE[slot] = edge_dst[rowE[slot]];
    y0v[slot]  = edge_attr[rowE[slot] * 4];
  }

  // stage W1 frags -> B0, chunk0 -> B1
  stage(t, sB0, &g_B1[0][0][0][0]);
  stage(t, sB1, &g_B2[0][0][0][0][0]);
  __syncthreads();

  // ---- GEMM1: D = dist @ W1 (fp16 a-split, 2 passes), one 16-row mtile ----
  float acc1[8][4];
  #pragma unroll
  for (int nt = 0; nt < 8; nt++)
    #pragma unroll
    for (int i = 0; i < 4; i++) acc1[nt][i] = 0.f;

  #pragma unroll
  for (int kt = 0; kt < 4; kt++) {
    u32 ah[4], al[4];
    {
      const int row0 = 16 * w + g;
      const float* dp = dist + (long)(e0 + row0) * 64 + kt * 16 + 2 * c;
      float2 f0 = *(const float2*)(dp);
      float2 f1 = *(const float2*)(dp + 8 * 64);
      float2 f2 = *(const float2*)(dp + 8);
      float2 f3 = *(const float2*)(dp + 8 * 64 + 8);
      split_pack_h(f0.x, f0.y, ah[0], al[0]);
      split_pack_h(f1.x, f1.y, ah[1], al[1]);
      split_pack_h(f2.x, f2.y, ah[2], al[2]);
      split_pack_h(f3.x, f3.y, ah[3], al[3]);
    }
    #pragma unroll
    for (int nt = 0; nt < 8; nt++) {
      u32 b[2];
      *(uint2*)b = *(const uint2*)&sB0[((kt * 8 + nt) * 32 + lane) * 2];
      mma16816h(acc1[nt], ah, b);
      mma16816h(acc1[nt], al, b);
    }
  }
  __syncthreads();                       // all warps done reading B0 (W1)
  stage(t, sB0, &g_B2[1][0][0][0][0]);   // chunk1 -> B0

  // silu on accumulators, pack directly into GEMM2 A fragments
  u32 A2h[4][4], A2l[4][4];
  #pragma unroll
  for (int kt = 0; kt < 4; kt++)
    #pragma unroll
    for (int idx = 0; idx < 4; idx++) {
      const int nt = 2 * kt + (idx >> 1);
      const int o  = (idx & 1) * 2;
      float v0 = acc1[nt][o + 0] * 0.125f;
      float v1 = acc1[nt][o + 1] * 0.125f;
      float h0 = SILU_NORM * v0 / (1.f + __expf(-v0));
      float h1 = SILU_NORM * v1 / (1.f + __expf(-v1));
      split_pack_h(h0, h1, A2h[kt][idx], A2l[kt][idx]);
    }

  // x0 fragment values: x0 at j in {2c,2c+1,8+2c,8+2c+1} for each of 2 rows
  float x0v[2][4];
  #pragma unroll
  for (int slot = 0; slot < 2; slot++) {
    const float* xp = node_input + (long)dstE[slot] * 40;
    float2 a = *(const float2*)(xp + 2 * c);
    float2 b = *(const float2*)(xp + 8 + 2 * c);
    x0v[slot][0] = a.x;  x0v[slot][1] = a.y;
    x0v[slot][2] = b.x;  x0v[slot][3] = b.y;
  }

  float oA[2][4];  float oB[2][2][3];
  #pragma unroll
  for (int s = 0; s < 2; s++) {
    #pragma unroll
    for (int i = 0; i < 4; i++) oA[s][i] = 0.f;
    #pragma unroll
    for (int p = 0; p < 2; p++)
      #pragma unroll
      for (int i = 0; i < 3; i++) oB[s][p][i] = 0.f;
  }

  #define CH(G, BUF) chunk_proc<G>(lane, c, BUF, A2h, A2l, x0v, y0v, rowE, dstE, \
                                   node_input, edge_attr, oA, oB)
  CH(0, sB1);  __syncthreads();  stage(t, sB1, &g_B2[2][0][0][0][0]);
  CH(1, sB0);  __syncthreads();  stage(t, sB0, &g_B2[3][0][0][0][0]);
  CH(2, sB1);  __syncthreads();  stage(t, sB1, &g_B2[4][0][0][0][0]);
  CH(3, sB0);  __syncthreads();  stage(t, sB0, &g_B2[5][0][0][0][0]);
  CH(4, sB1);  __syncthreads();  stage(t, sB1, &g_B2[6][0][0][0][0]);
  CH(5, sB0);  __syncthreads();  stage(t, sB0, &g_B2[7][0][0][0][0]);

  // scatter o0 outputs now (complete after w1 + w4 chunks); frees registers
  #pragma unroll
  for (int slot = 0; slot < 2; slot++) {
    const int base = edge_src[rowE[slot]] * 40;
    #pragma unroll
    for (int m = 0; m < 4; m++)
      atomicAdd(out + base + c + 4 * m, S0F * oA[slot][m]);
  }

  CH(6, sB1);  __syncthreads();  stage(t, sB1, &g_B2[8][0][0][0][0]);
  CH(7, sB0);  __syncthreads();
  CH(8, sB1);
  #undef CH

  // scatter o1 outputs
  #pragma unroll
  for (int slot = 0; slot < 2; slot++) {
    const int base = edge_src[rowE[slot]] * 40;
    #pragma unroll
    for (int sp = 0; sp < 2; sp++)
      #pragma unroll
      for (int i = 0; i < 3; i++)
        atomicAdd(out + base + 16 + (2 * c + sp) * 3 + i,
                  S0F * oB[slot][sp][i]);
  }
}

extern "C" void kernel_launch(void* const* d_in, const int* in_sizes, int n_in,
                              void* d_out, int out_size) {
  const float* node_input = (const float*)d_in[0];
  const int*   edge_src   = (const int*)d_in[1];
  const int*   edge_dst   = (const int*)d_in[2];
  const float* edge_attr  = (const float*)d_in[3];
  const float* dist       = (const float*)d_in[4];
  const float* W1         = (const float*)d_in[5];
  const float* W2         = (const float*)d_in[6];
  float* out = (float*)d_out;

  cudaMemsetAsync(out, 0, (size_t)out_size * sizeof(float));
  prep_frags<<<80, 128>>>(W1, W2);
  fused_conv<<<NBLK, 256, SMEM_BYTES>>>(node_input, edge_src, edge_dst,
                                        edge_attr, dist, out);
}

// round 13
// speedup vs baseline: 1.0221x; 1.0221x over previous
#include <cuda_runtime.h>
#include <cuda_fp16.h>
#include <cstdint>

#define N_EDGES   400000
#define TE        128
#define NBLK      (N_EDGES / TE)   // 3125, exact
#define WN        576
#define C3F       0.5773502691896257f
#define S0F       0.006378879538497861f   // sqrt(1/24)/32
#define SILU_NORM 1.6791767923989418f

typedef uint32_t u32;

// ---- weight fragment tables (fp16, mma.sync fragment order) ----------------
// L1-resident read-only tables (80 KB total): read via LDG, no smem staging.
__device__ u32 g_B2[9][4][8][32][2];
__device__ u32 g_B1[4][8][32][2];

__device__ __forceinline__ int w2col(int mp) {
  int j = mp & 15, gr = mp >> 4, g = gr >> 2, r = gr & 3;
  if (g < 4) return j * 16 + r + 4 * g;
  if (g < 6) return 448 + (j & 7) * 16 + r + 4 * ((g - 4) * 2 + (j >> 3));
  if (g < 8) return 256 + j * 8 + 2 * r + (g - 6);
  return 384 + (j & 7) * 8 + 2 * r + (j >> 3);
}

__device__ __forceinline__ void split_pack_h(float v0, float v1, u32 &hi, u32 &lo) {
  __half h0 = __float2half_rn(v0), h1 = __float2half_rn(v1);
  __half l0 = __float2half_rn(v0 - __half2float(h0));
  __half l1 = __float2half_rn(v1 - __half2float(h1));
  __half2 H; H.x = h0; H.y = h1;
  __half2 L; L.x = l0; L.y = l1;
  hi = *(u32*)&H;  lo = *(u32*)&L;
}
__device__ __forceinline__ u32 pack_h(float v0, float v1) {
  __half2 H; H.x = __float2half_rn(v0); H.y = __float2half_rn(v1);
  return *(u32*)&H;
}

__global__ void prep_frags(const float* __restrict__ W1,
                           const float* __restrict__ W2) {
  int idx = blockIdx.x * blockDim.x + threadIdx.x;
  if (idx >= 10240) return;
  int lane = idx & 31;
  int nt = (idx >> 5) & 7;
  int kt = (idx >> 8) & 3;
  int C  = idx >> 10;                 // 0..8 = W2 chunks, 9 = W1
  int g = lane >> 2, c = lane & 3;
  int n = nt * 8 + g;
  #pragma unroll
  for (int r = 0; r < 2; r++) {
    int k = kt * 16 + c * 2 + r * 8;
    float v0, v1;
    if (C < 9) {
      int m = w2col(C * 64 + n);
      v0 = W2[k * WN + m];  v1 = W2[(k + 1) * WN + m];
    } else {
      v0 = W1[k * 64 + n];  v1 = W1[(k + 1) * 64 + n];
    }
    u32 hv = pack_h(v0, v1);
    if (C < 9) g_B2[C][kt][nt][lane][r] = hv;
    else       g_B1[kt][nt][lane][r]    = hv;
  }
}

__device__ __forceinline__ void mma16816h(float (&d)[4], const u32 (&a)[4],
                                          const u32 (&b)[2]) {
  asm volatile(
      "mma.sync.aligned.m16n8k16.row.col.f32.f16.f16.f32 "
      "{%0,%1,%2,%3}, {%4,%5,%6,%7}, {%8,%9}, {%0,%1,%2,%3};"
      : "+f"(d[0]), "+f"(d[1]), "+f"(d[2]), "+f"(d[3])
      : "r"(a[0]), "r"(a[1]), "r"(a[2]), "r"(a[3]), "r"(b[0]), "r"(b[1]));
}

// ---- fragment-side epilogue for one half (nt = 4h..4h+3) -------------------
template <int G>
__device__ __forceinline__ void epi_half(
    int h, int c, const float (&acc)[2][4][4],
    const float (&x0v)[4][4], const float (&y0v)[4],
    const float (&z4v)[4][2], const float (&y1v)[4][3], const float (&x1v)[4][6],
    float (&oA)[4][4], float (&oB)[4][2][3])
{
  if (G < 4 || G == 6 || G == 7) {            // x0-dot classes (w1, w2)
    float P[4][2] = {};
    #pragma unroll
    for (int q = 0; q < 4; q++) {
      const int rrl = q >> 1, js = (q & 1) * 2;
      #pragma unroll
      for (int mt = 0; mt < 2; mt++) {
        P[2*mt+0][rrl] += acc[mt][q][0]*x0v[2*mt+0][js] + acc[mt][q][1]*x0v[2*mt+0][js+1];
        P[2*mt+1][rrl] += acc[mt][q][2]*x0v[2*mt+1][js] + acc[mt][q][3]*x0v[2*mt+1][js+1];
      }
    }
    #pragma unroll
    for (int rrl = 0; rrl < 2; rrl++)
      #pragma unroll
      for (int slot = 0; slot < 4; slot++) {
        float v = P[slot][rrl];
        v += __shfl_xor_sync(0xffffffffu, v, 1);
        v += __shfl_xor_sync(0xffffffffu, v, 2);
        if (c == 2*h + rrl) {
          if (G < 4) {
            oA[slot][G] += y0v[slot] * v;
          } else {
            oB[slot][G-6][0] += v * y1v[slot][0];
            oB[slot][G-6][1] += v * y1v[slot][1];
            oB[slot][G-6][2] += v * y1v[slot][2];
          }
        }
      }
  } else if (G < 6) {                          // w4: z4-dot, sA/sB per rr
    float P[4][2][2] = {};
    #pragma unroll
    for (int q = 0; q < 4; q++) {
      const int rrl = q >> 1, sel = q & 1;
      #pragma unroll
      for (int mt = 0; mt < 2; mt++) {
        P[2*mt+0][rrl][sel] += acc[mt][q][0]*z4v[2*mt+0][0] + acc[mt][q][1]*z4v[2*mt+0][1];
        P[2*mt+1][rrl][sel] += acc[mt][q][2]*z4v[2*mt+1][0] + acc[mt][q][3]*z4v[2*mt+1][1];
      }
    }
    #pragma unroll
    for (int rrl = 0; rrl < 2; rrl++)
      #pragma unroll
      for (int slot = 0; slot < 4; slot++)
        #pragma unroll
        for (int sel = 0; sel < 2; sel++) {
          float v = P[slot][rrl][sel];
          v += __shfl_xor_sync(0xffffffffu, v, 1);
          v += __shfl_xor_sync(0xffffffffu, v, 2);
          if (c == 2*h + rrl) oA[slot][2*(G-4)+sel] += C3F * v;
        }
  } else {                                     // G == 8, w3: x1-weighted
    #pragma unroll
    for (int q = 0; q < 4; q++) {
      const int rrl = q >> 1, hf = q & 1;
      float S[4][3] = {};
      #pragma unroll
      for (int mt = 0; mt < 2; mt++)
        #pragma unroll
        for (int i = 0; i < 3; i++) {
          S[2*mt+0][i] += acc[mt][q][0]*x1v[2*mt+0][i] + acc[mt][q][1]*x1v[2*mt+0][3+i];
          S[2*mt+1][i] += acc[mt][q][2]*x1v[2*mt+1][i] + acc[mt][q][3]*x1v[2*mt+1][3+i];
        }
      #pragma unroll
      for (int slot = 0; slot < 4; slot++)
        #pragma unroll
        for (int i = 0; i < 3; i++) {
          float v = S[slot][i];
          v += __shfl_xor_sync(0xffffffffu, v, 1);
          v += __shfl_xor_sync(0xffffffffu, v, 2);
          if (c == 2*h + rrl) oB[slot][hf][i] += y0v[slot] * v;
        }
    }
  }
}

// ---- one GEMM2 chunk: MMA (both halves) + fragment epilogue ----------------
template <int G>
__device__ __forceinline__ void chunk_proc(
    int lane, int c,
    const u32 (&A2h)[2][4][4], const u32 (&A2l)[2][4][4],
    const float (&x0v)[4][4], const float (&y0v)[4],
    const int (&rowE)[4], const int (&dstE)[4],
    const float* __restrict__ node_input, const float* __restrict__ edge_attr,
    float (&oA)[4][4], float (&oB)[4][2][3])
{
  float z4v[4][2];  float y1v[4][3];  float x1v[4][6];
  if (G == 4 || G == 5) {
    #pragma unroll
    for (int slot = 0; slot < 4; slot++) {
      float4 ya = ((const float4*)edge_attr)[rowE[slot]];
      const float* xp = node_input + (long)dstE[slot] * 40 + 16 + 6 * c;
      z4v[slot][0] = xp[0]*ya.y + xp[1]*ya.z + xp[2]*ya.w;
      z4v[slot][1] = xp[3]*ya.y + xp[4]*ya.z + xp[5]*ya.w;
    }
  }
  if (G == 6 || G == 7) {
    #pragma unroll
    for (int slot = 0; slot < 4; slot++) {
      float4 ya = ((const float4*)edge_attr)[rowE[slot]];
      y1v[slot][0] = ya.y;  y1v[slot][1] = ya.z;  y1v[slot][2] = ya.w;
    }
  }
  if (G == 8) {
    #pragma unroll
    for (int slot = 0; slot < 4; slot++) {
      const float* xp = node_input + (long)dstE[slot] * 40 + 16 + 6 * c;
      #pragma unroll
      for (int i = 0; i < 6; i++) x1v[slot][i] = xp[i];
    }
  }

  #pragma unroll
  for (int h = 0; h < 2; h++) {
    float acc[2][4][4];
    #pragma unroll
    for (int mt = 0; mt < 2; mt++)
      #pragma unroll
      for (int q = 0; q < 4; q++)
        #pragma unroll
        for (int i = 0; i < 4; i++) acc[mt][q][i] = 0.f;

    #pragma unroll
    for (int kt = 0; kt < 4; kt++)
      #pragma unroll
      for (int q = 0; q < 4; q++) {
        const int nt = 4 * h + q;
        uint2 bv = __ldg((const uint2*)&g_B2[G][kt][nt][lane][0]);
        u32 b[2] = {bv.x, bv.y};
        #pragma unroll
        for (int mt = 0; mt < 2; mt++) {
          mma16816h(acc[mt][q], A2h[mt][kt], b);
          mma16816h(acc[mt][q], A2l[mt][kt], b);
        }
      }
    epi_half<G>(h, c, acc, x0v, y0v, z4v, y1v, x1v, oA, oB);
  }
}

// ---- main kernel ------------------------------------------------------------
__global__ __launch_bounds__(128, 3) void fused_conv(
    const float* __restrict__ node_input,
    const int*   __restrict__ edge_src,
    const int*   __restrict__ edge_dst,
    const float* __restrict__ edge_attr,
    const float* __restrict__ dist,
    float* __restrict__ out)
{
  const int t = threadIdx.x;
  const int lane = t & 31, w = t >> 5;
  const int g = lane >> 2, c = lane & 3;
  const int e0 = blockIdx.x * TE;

  // per-lane row metadata (4 rows: slot = 2*mt + s -> row 32w+16mt+8s+g)
  int rowE[4], dstE[4];
  float y0v[4];
  #pragma unroll
  for (int slot = 0; slot < 4; slot++) {
    rowE[slot] = e0 + 32 * w + 16 * (slot >> 1) + 8 * (slot & 1) + g;
    dstE[slot] = edge_dst[rowE[slot]];
    y0v[slot]  = edge_attr[rowE[slot] * 4];
  }

  // ---- GEMM1: D = dist @ W1 (fp16 a-split, 2 passes), B frags via LDG ----
  float acc1[2][8][4];
  #pragma unroll
  for (int mt = 0; mt < 2; mt++)
    #pragma unroll
    for (int nt = 0; nt < 8; nt++)
      #pragma unroll
      for (int i = 0; i < 4; i++) acc1[mt][nt][i] = 0.f;

  #pragma unroll
  for (int kt = 0; kt < 4; kt++) {
    u32 ah[2][4], al[2][4];
    #pragma unroll
    for (int mt = 0; mt < 2; mt++) {
      const int row0 = 32 * w + 16 * mt + g;
      const float* dp = dist + (long)(e0 + row0) * 64 + kt * 16 + 2 * c;
      float2 f0 = *(const float2*)(dp);
      float2 f1 = *(const float2*)(dp + 8 * 64);
      float2 f2 = *(const float2*)(dp + 8);
      float2 f3 = *(const float2*)(dp + 8 * 64 + 8);
      split_pack_h(f0.x, f0.y, ah[mt][0], al[mt][0]);
      split_pack_h(f1.x, f1.y, ah[mt][1], al[mt][1]);
      split_pack_h(f2.x, f2.y, ah[mt][2], al[mt][2]);
      split_pack_h(f3.x, f3.y, ah[mt][3], al[mt][3]);
    }
    #pragma unroll
    for (int nt = 0; nt < 8; nt++) {
      uint2 bv = __ldg((const uint2*)&g_B1[kt][nt][lane][0]);
      u32 b[2] = {bv.x, bv.y};
      #pragma unroll
      for (int mt = 0; mt < 2; mt++) {
        mma16816h(acc1[mt][nt], ah[mt], b);
        mma16816h(acc1[mt][nt], al[mt], b);
      }
    }
  }

  // silu on accumulators, pack directly into GEMM2 A fragments (no smem)
  u32 A2h[2][4][4], A2l[2][4][4];
  #pragma unroll
  for (int mt = 0; mt < 2; mt++)
    #pragma unroll
    for (int kt = 0; kt < 4; kt++)
      #pragma unroll
      for (int idx = 0; idx < 4; idx++) {
        const int nt = 2 * kt + (idx >> 1);
        const int o  = (idx & 1) * 2;
        float v0 = acc1[mt][nt][o + 0] * 0.125f;
        float v1 = acc1[mt][nt][o + 1] * 0.125f;
        float h0 = SILU_NORM * v0 / (1.f + __expf(-v0));
        float h1 = SILU_NORM * v1 / (1.f + __expf(-v1));
        split_pack_h(h0, h1, A2h[mt][kt][idx], A2l[mt][kt][idx]);
      }

  // x0 fragment values: x0 at j in {2c,2c+1,8+2c,8+2c+1} for each of 4 rows
  float x0v[4][4];
  #pragma unroll
  for (int slot = 0; slot < 4; slot++) {
    const float* xp = node_input + (long)dstE[slot] * 40;
    float2 a = *(const float2*)(xp + 2 * c);
    float2 b = *(const float2*)(xp + 8 + 2 * c);
    x0v[slot][0] = a.x;  x0v[slot][1] = a.y;
    x0v[slot][2] = b.x;  x0v[slot][3] = b.y;
  }

  float oA[4][4];  float oB[4][2][3];
  #pragma unroll
  for (int s = 0; s < 4; s++) {
    #pragma unroll
    for (int i = 0; i < 4; i++) oA[s][i] = 0.f;
    #pragma unroll
    for (int p = 0; p < 2; p++)
      #pragma unroll
      for (int i = 0; i < 3; i++) oB[s][p][i] = 0.f;
  }

  #define CH(G) chunk_proc<G>(lane, c, A2h, A2l, x0v, y0v, rowE, dstE, \
                              node_input, edge_attr, oA, oB)
  CH(0);  CH(1);  CH(2);  CH(3);  CH(4);  CH(5);

  // scatter o0 outputs now (complete after w1 + w4 chunks); frees registers
  #pragma unroll
  for (int slot = 0; slot < 4; slot++) {
    const int base = edge_src[rowE[slot]] * 40;
    #pragma unroll
    for (int m = 0; m < 4; m++)
      atomicAdd(out + base + c + 4 * m, S0F * oA[slot][m]);
  }

  CH(6);  CH(7);  CH(8);
  #undef CH

  // scatter o1 outputs
  #pragma unroll
  for (int slot = 0; slot < 4; slot++) {
    const int base = edge_src[rowE[slot]] * 40;
    #pragma unroll
    for (int sp = 0; sp < 2; sp++)
      #pragma unroll
      for (int i = 0; i < 3; i++)
        atomicAdd(out + base + 16 + (2 * c + sp) * 3 + i,
                  S0F * oB[slot][sp][i]);
  }
}

extern "C" void kernel_launch(void* const* d_in, const int* in_sizes, int n_in,
                              void* d_out, int out_size) {
  const float* node_input = (const float*)d_in[0];
  const int*   edge_src   = (const int*)d_in[1];
  const int*   edge_dst   = (const int*)d_in[2];
  const float* edge_attr  = (const float*)d_in[3];
  const float* dist       = (const float*)d_in[4];
  const float* W1         = (const float*)d_in[5];
  const float* W2         = (const float*)d_in[6];
  float* out = (float*)d_out;

  cudaMemsetAsync(out, 0, (size_t)out_size * sizeof(float));
  prep_frags<<<80, 128>>>(W1, W2);
  fused_conv<<<NBLK, 128>>>(node_input, edge_src, edge_dst,
                            edge_attr, dist, out);
}

// round 14
// speedup vs baseline: 1.2768x; 1.2492x over previous
#include <cuda_runtime.h>
#include <cuda_fp16.h>
#include <cstdint>

#define N_EDGES   400000
#define TE        128
#define NBLK      (N_EDGES / TE)   // 3125, exact
#define WN        576
#define C3F       0.5773502691896257f
#define S0F       0.006378879538497861f   // sqrt(1/24)/32
#define SILU_NORM 1.6791767923989418f

typedef uint32_t u32;

// ---- weight fragment tables (fp16, mma.sync fragment order) ----------------
__device__ u32 g_B2[9][4][8][32][2];
__device__ u32 g_B1[4][8][32][2];

__device__ __forceinline__ int w2col(int mp) {
  int j = mp & 15, gr = mp >> 4, g = gr >> 2, r = gr & 3;
  if (g < 4) return j * 16 + r + 4 * g;
  if (g < 6) return 448 + (j & 7) * 16 + r + 4 * ((g - 4) * 2 + (j >> 3));
  if (g < 8) return 256 + j * 8 + 2 * r + (g - 6);
  return 384 + (j & 7) * 8 + 2 * r + (j >> 3);
}

__device__ __forceinline__ void split_pack_h(float v0, float v1, u32 &hi, u32 &lo) {
  __half h0 = __float2half_rn(v0), h1 = __float2half_rn(v1);
  __half l0 = __float2half_rn(v0 - __half2float(h0));
  __half l1 = __float2half_rn(v1 - __half2float(h1));
  __half2 H; H.x = h0; H.y = h1;
  __half2 L; L.x = l0; L.y = l1;
  hi = *(u32*)&H;  lo = *(u32*)&L;
}
__device__ __forceinline__ u32 pack_h(float v0, float v1) {
  __half2 H; H.x = __float2half_rn(v0); H.y = __float2half_rn(v1);
  return *(u32*)&H;
}

__global__ void prep_frags(const float* __restrict__ W1,
                           const float* __restrict__ W2) {
  int idx = blockIdx.x * blockDim.x + threadIdx.x;
  if (idx >= 10240) return;
  int lane = idx & 31;
  int nt = (idx >> 5) & 7;
  int kt = (idx >> 8) & 3;
  int C  = idx >> 10;                 // 0..8 = W2 chunks, 9 = W1
  int g = lane >> 2, c = lane & 3;
  int n = nt * 8 + g;
  #pragma unroll
  for (int r = 0; r < 2; r++) {
    int k = kt * 16 + c * 2 + r * 8;
    float v0, v1;
    if (C < 9) {
      int m = w2col(C * 64 + n);
      v0 = W2[k * WN + m];  v1 = W2[(k + 1) * WN + m];
    } else {
      v0 = W1[k * 64 + n];  v1 = W1[(k + 1) * 64 + n];
    }
    u32 hv = pack_h(v0, v1);
    if (C < 9) g_B2[C][kt][nt][lane][r] = hv;
    else       g_B1[kt][nt][lane][r]    = hv;
  }
}

__device__ __forceinline__ void mma16816h(float (&d)[4], const u32 (&a)[4],
                                          const u32 (&b)[2]) {
  asm volatile(
      "mma.sync.aligned.m16n8k16.row.col.f32.f16.f16.f32 "
      "{%0,%1,%2,%3}, {%4,%5,%6,%7}, {%8,%9}, {%0,%1,%2,%3};"
      : "+f"(d[0]), "+f"(d[1]), "+f"(d[2]), "+f"(d[3])
      : "r"(a[0]), "r"(a[1]), "r"(a[2]), "r"(a[3]), "r"(b[0]), "r"(b[1]));
}

#define SMEM_BYTES 16384   // two 8KB fp16 B buffers

__device__ __forceinline__ void stage(int t, u32* dst, const u32* src) {
  #pragma unroll
  for (int i = 0; i < 4; i++)
    ((uint4*)dst)[t + i * 128] = ((const uint4*)src)[t + i * 128];
}

// ---- fragment-side epilogue for one half (nt = 4h..4h+3) -------------------
template <int G>
__device__ __forceinline__ void epi_half(
    int h, int c, const float (&acc)[2][4][4],
    const float (&x0v)[4][4], const float (&y0v)[4],
    const float (&z4v)[4][2], const float (&y1v)[4][3], const float (&x1v)[4][6],
    float (&oA)[4][4], float (&oB)[4][2][3])
{
  if (G < 4 || G == 6 || G == 7) {            // x0-dot classes (w1, w2)
    float P[4][2] = {};
    #pragma unroll
    for (int q = 0; q < 4; q++) {
      const int rrl = q >> 1, js = (q & 1) * 2;
      #pragma unroll
      for (int mt = 0; mt < 2; mt++) {
        P[2*mt+0][rrl] += acc[mt][q][0]*x0v[2*mt+0][js] + acc[mt][q][1]*x0v[2*mt+0][js+1];
        P[2*mt+1][rrl] += acc[mt][q][2]*x0v[2*mt+1][js] + acc[mt][q][3]*x0v[2*mt+1][js+1];
      }
    }
    #pragma unroll
    for (int rrl = 0; rrl < 2; rrl++)
      #pragma unroll
      for (int slot = 0; slot < 4; slot++) {
        float v = P[slot][rrl];
        v += __shfl_xor_sync(0xffffffffu, v, 1);
        v += __shfl_xor_sync(0xffffffffu, v, 2);
        if (c == 2*h + rrl) {
          if (G < 4) {
            oA[slot][G] += y0v[slot] * v;
          } else {
            oB[slot][G-6][0] += v * y1v[slot][0];
            oB[slot][G-6][1] += v * y1v[slot][1];
            oB[slot][G-6][2] += v * y1v[slot][2];
          }
        }
      }
  } else if (G < 6) {                          // w4: z4-dot, sA/sB per rr
    float P[4][2][2] = {};
    #pragma unroll
    for (int q = 0; q < 4; q++) {
      const int rrl = q >> 1, sel = q & 1;
      #pragma unroll
      for (int mt = 0; mt < 2; mt++) {
        P[2*mt+0][rrl][sel] += acc[mt][q][0]*z4v[2*mt+0][0] + acc[mt][q][1]*z4v[2*mt+0][1];
        P[2*mt+1][rrl][sel] += acc[mt][q][2]*z4v[2*mt+1][0] + acc[mt][q][3]*z4v[2*mt+1][1];
      }
    }
    #pragma unroll
    for (int rrl = 0; rrl < 2; rrl++)
      #pragma unroll
      for (int slot = 0; slot < 4; slot++)
        #pragma unroll
        for (int sel = 0; sel < 2; sel++) {
          float v = P[slot][rrl][sel];
          v += __shfl_xor_sync(0xffffffffu, v, 1);
          v += __shfl_xor_sync(0xffffffffu, v, 2);
          if (c == 2*h + rrl) oA[slot][2*(G-4)+sel] += C3F * v;
        }
  } else {                                     // G == 8, w3: x1-weighted
    #pragma unroll
    for (int q = 0; q < 4; q++) {
      const int rrl = q >> 1, hf = q & 1;
      float S[4][3] = {};
      #pragma unroll
      for (int mt = 0; mt < 2; mt++)
        #pragma unroll
        for (int i = 0; i < 3; i++) {
          S[2*mt+0][i] += acc[mt][q][0]*x1v[2*mt+0][i] + acc[mt][q][1]*x1v[2*mt+0][3+i];
          S[2*mt+1][i] += acc[mt][q][2]*x1v[2*mt+1][i] + acc[mt][q][3]*x1v[2*mt+1][3+i];
        }
      #pragma unroll
      for (int slot = 0; slot < 4; slot++)
        #pragma unroll
        for (int i = 0; i < 3; i++) {
          float v = S[slot][i];
          v += __shfl_xor_sync(0xffffffffu, v, 1);
          v += __shfl_xor_sync(0xffffffffu, v, 2);
          if (c == 2*h + rrl) oB[slot][hf][i] += y0v[slot] * v;
        }
    }
  }
}

// ---- one GEMM2 chunk: MMA (both halves, single A pass) + epilogue ----------
template <int G>
__device__ __forceinline__ void chunk_proc(
    int lane, int c, const u32* __restrict__ bcur,
    const u32 (&A2)[2][4][4],
    const float (&x0v)[4][4], const float (&y0v)[4],
    const int (&rowE)[4], const int (&dstE)[4],
    const float* __restrict__ node_input, const float* __restrict__ edge_attr,
    float (&oA)[4][4], float (&oB)[4][2][3])
{
  float z4v[4][2];  float y1v[4][3];  float x1v[4][6];
  if (G == 4 || G == 5) {
    #pragma unroll
    for (int slot = 0; slot < 4; slot++) {
      float4 ya = ((const float4*)edge_attr)[rowE[slot]];
      const float* xp = node_input + (long)dstE[slot] * 40 + 16 + 6 * c;
      z4v[slot][0] = xp[0]*ya.y + xp[1]*ya.z + xp[2]*ya.w;
      z4v[slot][1] = xp[3]*ya.y + xp[4]*ya.z + xp[5]*ya.w;
    }
  }
  if (G == 6 || G == 7) {
    #pragma unroll
    for (int slot = 0; slot < 4; slot++) {
      float4 ya = ((const float4*)edge_attr)[rowE[slot]];
      y1v[slot][0] = ya.y;  y1v[slot][1] = ya.z;  y1v[slot][2] = ya.w;
    }
  }
  if (G == 8) {
    #pragma unroll
    for (int slot = 0; slot < 4; slot++) {
      const float* xp = node_input + (long)dstE[slot] * 40 + 16 + 6 * c;
      #pragma unroll
      for (int i = 0; i < 6; i++) x1v[slot][i] = xp[i];
    }
  }

  #pragma unroll
  for (int h = 0; h < 2; h++) {
    float acc[2][4][4];
    #pragma unroll
    for (int mt = 0; mt < 2; mt++)
      #pragma unroll
      for (int q = 0; q < 4; q++)
        #pragma unroll
        for (int i = 0; i < 4; i++) acc[mt][q][i] = 0.f;

    #pragma unroll
    for (int kt = 0; kt < 4; kt++)
      #pragma unroll
      for (int q = 0; q < 4; q++) {
        const int nt = 4 * h + q;
        u32 b[2];
        *(uint2*)b = *(const uint2*)&bcur[((kt * 8 + nt) * 32 + lane) * 2];
        #pragma unroll
        for (int mt = 0; mt < 2; mt++)
          mma16816h(acc[mt][q], A2[mt][kt], b);
      }
    epi_half<G>(h, c, acc, x0v, y0v, z4v, y1v, x1v, oA, oB);
  }
}

// ---- main kernel ------------------------------------------------------------
__global__ __launch_bounds__(128, 3) void fused_conv(
    const float* __restrict__ node_input,
    const int*   __restrict__ edge_src,
    const int*   __restrict__ edge_dst,
    const float* __restrict__ edge_attr,
    const float* __restrict__ dist,
    float* __restrict__ out)
{
  extern __shared__ u32 smu[];
  u32* sB0 = smu;
  u32* sB1 = smu + 2048;

  const int t = threadIdx.x;
  const int lane = t & 31, w = t >> 5;
  const int g = lane >> 2, c = lane & 3;
  const int e0 = blockIdx.x * TE;

  // per-lane row metadata (4 rows: slot = 2*mt + s -> row 32w+16mt+8s+g)
  int rowE[4], dstE[4];
  float y0v[4];
  #pragma unroll
  for (int slot = 0; slot < 4; slot++) {
    rowE[slot] = e0 + 32 * w + 16 * (slot >> 1) + 8 * (slot & 1) + g;
    dstE[slot] = edge_dst[rowE[slot]];
    y0v[slot]  = edge_attr[rowE[slot] * 4];
  }

  // stage W1 frags -> B0, chunk0 -> B1
  stage(t, sB0, &g_B1[0][0][0][0]);
  stage(t, sB1, &g_B2[0][0][0][0][0]);
  __syncthreads();

  // ---- GEMM1: D = dist @ W1 (fp16 a-split, 2 passes) ----
  float acc1[2][8][4];
  #pragma unroll
  for (int mt = 0; mt < 2; mt++)
    #pragma unroll
    for (int nt = 0; nt < 8; nt++)
      #pragma unroll
      for (int i = 0; i < 4; i++) acc1[mt][nt][i] = 0.f;

  #pragma unroll
  for (int kt = 0; kt < 4; kt++) {
    u32 ah[2][4], al[2][4];
    #pragma unroll
    for (int mt = 0; mt < 2; mt++) {
      const int row0 = 32 * w + 16 * mt + g;
      const float* dp = dist + (long)(e0 + row0) * 64 + kt * 16 + 2 * c;
      float2 f0 = *(const float2*)(dp);
      float2 f1 = *(const float2*)(dp + 8 * 64);
      float2 f2 = *(const float2*)(dp + 8);
      float2 f3 = *(const float2*)(dp + 8 * 64 + 8);
      split_pack_h(f0.x, f0.y, ah[mt][0], al[mt][0]);
      split_pack_h(f1.x, f1.y, ah[mt][1], al[mt][1]);
      split_pack_h(f2.x, f2.y, ah[mt][2], al[mt][2]);
      split_pack_h(f3.x, f3.y, ah[mt][3], al[mt][3]);
    }
    #pragma unroll
    for (int nt = 0; nt < 8; nt++) {
      u32 b[2];
      *(uint2*)b = *(const uint2*)&sB0[((kt * 8 + nt) * 32 + lane) * 2];
      #pragma unroll
      for (int mt = 0; mt < 2; mt++) {
        mma16816h(acc1[mt][nt], ah[mt], b);
        mma16816h(acc1[mt][nt], al[mt], b);
      }
    }
  }
  __syncthreads();                       // all warps done reading B0 (W1)
  stage(t, sB0, &g_B2[1][0][0][0][0]);   // chunk1 -> B0

  // silu on accumulators, pack directly into GEMM2 A fragments (single fp16)
  u32 A2[2][4][4];
  #pragma unroll
  for (int mt = 0; mt < 2; mt++)
    #pragma unroll
    for (int kt = 0; kt < 4; kt++)
      #pragma unroll
      for (int idx = 0; idx < 4; idx++) {
        const int nt = 2 * kt + (idx >> 1);
        const int o  = (idx & 1) * 2;
        float v0 = acc1[mt][nt][o + 0] * 0.125f;
        float v1 = acc1[mt][nt][o + 1] * 0.125f;
        float h0 = SILU_NORM * v0 / (1.f + __expf(-v0));
        float h1 = SILU_NORM * v1 / (1.f + __expf(-v1));
        A2[mt][kt][idx] = pack_h(h0, h1);
      }

  // x0 fragment values: x0 at j in {2c,2c+1,8+2c,8+2c+1} for each of 4 rows
  float x0v[4][4];
  #pragma unroll
  for (int slot = 0; slot < 4; slot++) {
    const float* xp = node_input + (long)dstE[slot] * 40;
    float2 a = *(const float2*)(xp + 2 * c);
    float2 b = *(const float2*)(xp + 8 + 2 * c);
    x0v[slot][0] = a.x;  x0v[slot][1] = a.y;
    x0v[slot][2] = b.x;  x0v[slot][3] = b.y;
  }

  float oA[4][4];  float oB[4][2][3];
  #pragma unroll
  for (int s = 0; s < 4; s++) {
    #pragma unroll
    for (int i = 0; i < 4; i++) oA[s][i] = 0.f;
    #pragma unroll
    for (int p = 0; p < 2; p++)
      #pragma unroll
      for (int i = 0; i < 3; i++) oB[s][p][i] = 0.f;
  }

  #define CH(G, BUF) chunk_proc<G>(lane, c, BUF, A2, x0v, y0v, rowE, dstE, \
                                   node_input, edge_attr, oA, oB)
  CH(0, sB1);  __syncthreads();  stage(t, sB1, &g_B2[2][0][0][0][0]);
  CH(1, sB0);  __syncthreads();  stage(t, sB0, &g_B2[3][0][0][0][0]);
  CH(2, sB1);  __syncthreads();  stage(t, sB1, &g_B2[4][0][0][0][0]);
  CH(3, sB0);  __syncthreads();  stage(t, sB0, &g_B2[5][0][0][0][0]);
  CH(4, sB1);  __syncthreads();  stage(t, sB1, &g_B2[6][0][0][0][0]);
  CH(5, sB0);  __syncthreads();  stage(t, sB0, &g_B2[7][0][0][0][0]);

  // scatter o0 outputs now (complete after w1 + w4 chunks); frees registers
  #pragma unroll
  for (int slot = 0; slot < 4; slot++) {
    const int base = edge_src[rowE[slot]] * 40;
    #pragma unroll
    for (int m = 0; m < 4; m++)
      atomicAdd(out + base + c + 4 * m, S0F * oA[slot][m]);
  }

  CH(6, sB1);  __syncthreads();  stage(t, sB1, &g_B2[8][0][0][0][0]);
  CH(7, sB0);  __syncthreads();
  CH(8, sB1);
  #undef CH

  // scatter o1 outputs
  #pragma unroll
  for (int slot = 0; slot < 4; slot++) {
    const int base = edge_src[rowE[slot]] * 40;
    #pragma unroll
    for (int sp = 0; sp < 2; sp++)
      #pragma unroll
      for (int i = 0; i < 3; i++)
        atomicAdd(out + base + 16 + (2 * c + sp) * 3 + i,
                  S0F * oB[slot][sp][i]);
  }
}

extern "C" void kernel_launch(void* const* d_in, const int* in_sizes, int n_in,
                              void* d_out, int out_size) {
  const float* node_input = (const float*)d_in[0];
  const int*   edge_src   = (const int*)d_in[1];
  const int*   edge_dst   = (const int*)d_in[2];
  const float* edge_attr  = (const float*)d_in[3];
  const float* dist       = (const float*)d_in[4];
  const float* W1         = (const float*)d_in[5];
  const float* W2         = (const float*)d_in[6];
  float* out = (float*)d_out;

  cudaMemsetAsync(out, 0, (size_t)out_size * sizeof(float));
  prep_frags<<<80, 128>>>(W1, W2);
  fused_conv<<<NBLK, 128, SMEM_BYTES>>>(node_input, edge_src, edge_dst,
                                        edge_attr, dist, out);
}

// round 15
// speedup vs baseline: 1.3644x; 1.0686x over previous
#include <cuda_runtime.h>
#include <cuda_fp16.h>
#include <cstdint>

#define N_EDGES   400000
#define TE        128
#define NBLK      (N_EDGES / TE)   // 3125, exact
#define WN        576
#define C3F       0.5773502691896257f
#define S0F       0.006378879538497861f   // sqrt(1/24)/32
#define SILU_NORM 1.6791767923989418f

typedef uint32_t u32;

// ---- weight fragment tables (fp16, mma.sync fragment order) ----------------
__device__ u32 g_B2[9][4][8][32][2];
__device__ u32 g_B1[4][8][32][2];

__device__ __forceinline__ int w2col(int mp) {
  int j = mp & 15, gr = mp >> 4, g = gr >> 2, r = gr & 3;
  if (g < 4) return j * 16 + r + 4 * g;
  if (g < 6) return 448 + (j & 7) * 16 + r + 4 * ((g - 4) * 2 + (j >> 3));
  if (g < 8) return 256 + j * 8 + 2 * r + (g - 6);
  return 384 + (j & 7) * 8 + 2 * r + (j >> 3);
}

__device__ __forceinline__ u32 pack_h(float v0, float v1) {
  __half2 H; H.x = __float2half_rn(v0); H.y = __float2half_rn(v1);
  return *(u32*)&H;
}

__global__ void prep_frags(const float* __restrict__ W1,
                           const float* __restrict__ W2) {
  int idx = blockIdx.x * blockDim.x + threadIdx.x;
  if (idx >= 10240) return;
  int lane = idx & 31;
  int nt = (idx >> 5) & 7;
  int kt = (idx >> 8) & 3;
  int C  = idx >> 10;                 // 0..8 = W2 chunks, 9 = W1
  int g = lane >> 2, c = lane & 3;
  int n = nt * 8 + g;
  #pragma unroll
  for (int r = 0; r < 2; r++) {
    int k = kt * 16 + c * 2 + r * 8;
    float v0, v1;
    if (C < 9) {
      int m = w2col(C * 64 + n);
      v0 = W2[k * WN + m];  v1 = W2[(k + 1) * WN + m];
    } else {
      v0 = W1[k * 64 + n];  v1 = W1[(k + 1) * 64 + n];
    }
    u32 hv = pack_h(v0, v1);
    if (C < 9) g_B2[C][kt][nt][lane][r] = hv;
    else       g_B1[kt][nt][lane][r]    = hv;
  }
}

__device__ __forceinline__ void mma16816h(float (&d)[4], const u32 (&a)[4],
                                          const u32 (&b)[2]) {
  asm volatile(
      "mma.sync.aligned.m16n8k16.row.col.f32.f16.f16.f32 "
      "{%0,%1,%2,%3}, {%4,%5,%6,%7}, {%8,%9}, {%0,%1,%2,%3};"
      : "+f"(d[0]), "+f"(d[1]), "+f"(d[2]), "+f"(d[3])
      : "r"(a[0]), "r"(a[1]), "r"(a[2]), "r"(a[3]), "r"(b[0]), "r"(b[1]));
}

#define SMEM_BYTES 16384   // two 8KB fp16 B buffers

__device__ __forceinline__ void stage(int t, u32* dst, const u32* src) {
  #pragma unroll
  for (int i = 0; i < 4; i++)
    ((uint4*)dst)[t + i * 128] = ((const uint4*)src)[t + i * 128];
}

// ---- fragment-side epilogue for one half (nt = 4h..4h+3) -------------------
template <int G>
__device__ __forceinline__ void epi_half(
    int h, int c, const float (&acc)[2][4][4],
    const float (&x0v)[4][4], const float (&y0v)[4],
    const float (&z4v)[4][2], const float (&y1v)[4][3], const float (&x1v)[4][6],
    float (&oA)[4][4], float (&oB)[4][2][3])
{
  if (G < 4 || G == 6 || G == 7) {            // x0-dot classes (w1, w2)
    float P[4][2] = {};
    #pragma unroll
    for (int q = 0; q < 4; q++) {
      const int rrl = q >> 1, js = (q & 1) * 2;
      #pragma unroll
      for (int mt = 0; mt < 2; mt++) {
        P[2*mt+0][rrl] += acc[mt][q][0]*x0v[2*mt+0][js] + acc[mt][q][1]*x0v[2*mt+0][js+1];
        P[2*mt+1][rrl] += acc[mt][q][2]*x0v[2*mt+1][js] + acc[mt][q][3]*x0v[2*mt+1][js+1];
      }
    }
    #pragma unroll
    for (int rrl = 0; rrl < 2; rrl++)
      #pragma unroll
      for (int slot = 0; slot < 4; slot++) {
        float v = P[slot][rrl];
        v += __shfl_xor_sync(0xffffffffu, v, 1);
        v += __shfl_xor_sync(0xffffffffu, v, 2);
        if (c == 2*h + rrl) {
          if (G < 4) {
            oA[slot][G] += y0v[slot] * v;
          } else {
            oB[slot][G-6][0] += v * y1v[slot][0];
            oB[slot][G-6][1] += v * y1v[slot][1];
            oB[slot][G-6][2] += v * y1v[slot][2];
          }
        }
      }
  } else if (G < 6) {                          // w4: z4-dot, sA/sB per rr
    float P[4][2][2] = {};
    #pragma unroll
    for (int q = 0; q < 4; q++) {
      const int rrl = q >> 1, sel = q & 1;
      #pragma unroll
      for (int mt = 0; mt < 2; mt++) {
        P[2*mt+0][rrl][sel] += acc[mt][q][0]*z4v[2*mt+0][0] + acc[mt][q][1]*z4v[2*mt+0][1];
        P[2*mt+1][rrl][sel] += acc[mt][q][2]*z4v[2*mt+1][0] + acc[mt][q][3]*z4v[2*mt+1][1];
      }
    }
    #pragma unroll
    for (int rrl = 0; rrl < 2; rrl++)
      #pragma unroll
      for (int slot = 0; slot < 4; slot++)
        #pragma unroll
        for (int sel = 0; sel < 2; sel++) {
          float v = P[slot][rrl][sel];
          v += __shfl_xor_sync(0xffffffffu, v, 1);
          v += __shfl_xor_sync(0xffffffffu, v, 2);
          if (c == 2*h + rrl) oA[slot][2*(G-4)+sel] += C3F * v;
        }
  } else {                                     // G == 8, w3: x1-weighted
    #pragma unroll
    for (int q = 0; q < 4; q++) {
      const int rrl = q >> 1, hf = q & 1;
      float S[4][3] = {};
      #pragma unroll
      for (int mt = 0; mt < 2; mt++)
        #pragma unroll
        for (int i = 0; i < 3; i++) {
          S[2*mt+0][i] += acc[mt][q][0]*x1v[2*mt+0][i] + acc[mt][q][1]*x1v[2*mt+0][3+i];
          S[2*mt+1][i] += acc[mt][q][2]*x1v[2*mt+1][i] + acc[mt][q][3]*x1v[2*mt+1][3+i];
        }
      #pragma unroll
      for (int slot = 0; slot < 4; slot++)
        #pragma unroll
        for (int i = 0; i < 3; i++) {
          float v = S[slot][i];
          v += __shfl_xor_sync(0xffffffffu, v, 1);
          v += __shfl_xor_sync(0xffffffffu, v, 2);
          if (c == 2*h + rrl) oB[slot][hf][i] += y0v[slot] * v;
        }
    }
  }
}

// ---- one GEMM2 chunk: MMA (both halves, single A pass) + epilogue ----------
template <int G>
__device__ __forceinline__ void chunk_proc(
    int lane, int c, const u32* __restrict__ bcur,
    const u32 (&A2)[2][4][4],
    const float (&x0v)[4][4], const float (&y0v)[4],
    const int (&rowE)[4], const int (&dstE)[4],
    const float* __restrict__ node_input, const float* __restrict__ edge_attr,
    float (&oA)[4][4], float (&oB)[4][2][3])
{
  float z4v[4][2];  float y1v[4][3];  float x1v[4][6];
  if (G == 4 || G == 5) {
    #pragma unroll
    for (int slot = 0; slot < 4; slot++) {
      float4 ya = ((const float4*)edge_attr)[rowE[slot]];
      const float* xp = node_input + (long)dstE[slot] * 40 + 16 + 6 * c;
      z4v[slot][0] = xp[0]*ya.y + xp[1]*ya.z + xp[2]*ya.w;
      z4v[slot][1] = xp[3]*ya.y + xp[4]*ya.z + xp[5]*ya.w;
    }
  }
  if (G == 6 || G == 7) {
    #pragma unroll
    for (int slot = 0; slot < 4; slot++) {
      float4 ya = ((const float4*)edge_attr)[rowE[slot]];
      y1v[slot][0] = ya.y;  y1v[slot][1] = ya.z;  y1v[slot][2] = ya.w;
    }
  }
  if (G == 8) {
    #pragma unroll
    for (int slot = 0; slot < 4; slot++) {
      const float* xp = node_input + (long)dstE[slot] * 40 + 16 + 6 * c;
      #pragma unroll
      for (int i = 0; i < 6; i++) x1v[slot][i] = xp[i];
    }
  }

  #pragma unroll
  for (int h = 0; h < 2; h++) {
    float acc[2][4][4];
    #pragma unroll
    for (int mt = 0; mt < 2; mt++)
      #pragma unroll
      for (int q = 0; q < 4; q++)
        #pragma unroll
        for (int i = 0; i < 4; i++) acc[mt][q][i] = 0.f;

    #pragma unroll
    for (int kt = 0; kt < 4; kt++)
      #pragma unroll
      for (int q = 0; q < 4; q++) {
        const int nt = 4 * h + q;
        u32 b[2];
        *(uint2*)b = *(const uint2*)&bcur[((kt * 8 + nt) * 32 + lane) * 2];
        #pragma unroll
        for (int mt = 0; mt < 2; mt++)
          mma16816h(acc[mt][q], A2[mt][kt], b);
      }
    epi_half<G>(h, c, acc, x0v, y0v, z4v, y1v, x1v, oA, oB);
  }
}

// ---- main kernel ------------------------------------------------------------
__global__ __launch_bounds__(128, 4) void fused_conv(
    const float* __restrict__ node_input,
    const int*   __restrict__ edge_src,
    const int*   __restrict__ edge_dst,
    const float* __restrict__ edge_attr,
    const float* __restrict__ dist,
    float* __restrict__ out)
{
  extern __shared__ u32 smu[];
  u32* sB0 = smu;
  u32* sB1 = smu + 2048;

  const int t = threadIdx.x;
  const int lane = t & 31, w = t >> 5;
  const int g = lane >> 2, c = lane & 3;
  const int e0 = blockIdx.x * TE;

  // per-lane row metadata (4 rows: slot = 2*mt + s -> row 32w+16mt+8s+g)
  int rowE[4], dstE[4];
  float y0v[4];
  #pragma unroll
  for (int slot = 0; slot < 4; slot++) {
    rowE[slot] = e0 + 32 * w + 16 * (slot >> 1) + 8 * (slot & 1) + g;
    dstE[slot] = edge_dst[rowE[slot]];
    y0v[slot]  = edge_attr[rowE[slot] * 4];
  }

  // stage W1 frags -> B0, chunk0 -> B1
  stage(t, sB0, &g_B1[0][0][0][0]);
  stage(t, sB1, &g_B2[0][0][0][0][0]);
  __syncthreads();

  // ---- GEMM1: D = dist @ W1 (single-pass fp16 A), two n-halves ----
  // n-half nh covers GEMM1 cols 32nh..32nh+31 -> A2 fragments kt' = 2nh, 2nh+1
  u32 A2[2][4][4];
  #pragma unroll
  for (int nh = 0; nh < 2; nh++) {
    float acc1[2][4][4];
    #pragma unroll
    for (int mt = 0; mt < 2; mt++)
      #pragma unroll
      for (int q = 0; q < 4; q++)
        #pragma unroll
        for (int i = 0; i < 4; i++) acc1[mt][q][i] = 0.f;

    #pragma unroll
    for (int kt = 0; kt < 4; kt++) {
      u32 ah[2][4];
      #pragma unroll
      for (int mt = 0; mt < 2; mt++) {
        const int row0 = 32 * w + 16 * mt + g;
        const float* dp = dist + (long)(e0 + row0) * 64 + kt * 16 + 2 * c;
        float2 f0 = *(const float2*)(dp);
        float2 f1 = *(const float2*)(dp + 8 * 64);
        float2 f2 = *(const float2*)(dp + 8);
        float2 f3 = *(const float2*)(dp + 8 * 64 + 8);
        ah[mt][0] = pack_h(f0.x, f0.y);
        ah[mt][1] = pack_h(f1.x, f1.y);
        ah[mt][2] = pack_h(f2.x, f2.y);
        ah[mt][3] = pack_h(f3.x, f3.y);
      }
      #pragma unroll
      for (int q = 0; q < 4; q++) {
        const int nt = 4 * nh + q;
        u32 b[2];
        *(uint2*)b = *(const uint2*)&sB0[((kt * 8 + nt) * 32 + lane) * 2];
        #pragma unroll
        for (int mt = 0; mt < 2; mt++)
          mma16816h(acc1[mt][q], ah[mt], b);
      }
    }

    // silu + pack into A2 fragments for this half
    #pragma unroll
    for (int mt = 0; mt < 2; mt++)
      #pragma unroll
      for (int q = 0; q < 4; q++) {
        const int ktp = 2 * nh + (q >> 1);
        #pragma unroll
        for (int j = 0; j < 2; j++) {
          float v0 = acc1[mt][q][2 * j + 0] * 0.125f;
          float v1 = acc1[mt][q][2 * j + 1] * 0.125f;
          float h0 = SILU_NORM * v0 / (1.f + __expf(-v0));
          float h1 = SILU_NORM * v1 / (1.f + __expf(-v1));
          A2[mt][ktp][2 * (q & 1) + j] = pack_h(h0, h1);
        }
      }
  }
  __syncthreads();                       // all warps done reading B0 (W1)
  stage(t, sB0, &g_B2[1][0][0][0][0]);   // chunk1 -> B0

  // x0 fragment values: x0 at j in {2c,2c+1,8+2c,8+2c+1} for each of 4 rows
  float x0v[4][4];
  #pragma unroll
  for (int slot = 0; slot < 4; slot++) {
    const float* xp = node_input + (long)dstE[slot] * 40;
    float2 a = *(const float2*)(xp + 2 * c);
    float2 b = *(const float2*)(xp + 8 + 2 * c);
    x0v[slot][0] = a.x;  x0v[slot][1] = a.y;
    x0v[slot][2] = b.x;  x0v[slot][3] = b.y;
  }

  float oA[4][4];  float oB[4][2][3];
  #pragma unroll
  for (int s = 0; s < 4; s++) {
    #pragma unroll
    for (int i = 0; i < 4; i++) oA[s][i] = 0.f;
    #pragma unroll
    for (int p = 0; p < 2; p++)
      #pragma unroll
      for (int i = 0; i < 3; i++) oB[s][p][i] = 0.f;
  }

  #define CH(G, BUF) chunk_proc<G>(lane, c, BUF, A2, x0v, y0v, rowE, dstE, \
                                   node_input, edge_attr, oA, oB)
  CH(0, sB1);  __syncthreads();  stage(t, sB1, &g_B2[2][0][0][0][0]);
  CH(1, sB0);  __syncthreads();  stage(t, sB0, &g_B2[3][0][0][0][0]);
  CH(2, sB1);  __syncthreads();  stage(t, sB1, &g_B2[4][0][0][0][0]);
  CH(3, sB0);  __syncthreads();  stage(t, sB0, &g_B2[5][0][0][0][0]);
  CH(4, sB1);  __syncthreads();  stage(t, sB1, &g_B2[6][0][0][0][0]);
  CH(5, sB0);  __syncthreads();  stage(t, sB0, &g_B2[7][0][0][0][0]);

  // scatter o0 outputs now (complete after w1 + w4 chunks); frees registers
  #pragma unroll
  for (int slot = 0; slot < 4; slot++) {
    const int base = edge_src[rowE[slot]] * 40;
    #pragma unroll
    for (int m = 0; m < 4; m++)
      atomicAdd(out + base + c + 4 * m, S0F * oA[slot][m]);
  }

  CH(6, sB1);  __syncthreads();  stage(t, sB1, &g_B2[8][0][0][0][0]);
  CH(7, sB0);  __syncthreads();
  CH(8, sB1);
  #undef CH

  // scatter o1 outputs
  #pragma unroll
  for (int slot = 0; slot < 4; slot++) {
    const int base = edge_src[rowE[slot]] * 40;
    #pragma unroll
    for (int sp = 0; sp < 2; sp++)
      #pragma unroll
      for (int i = 0; i < 3; i++)
        atomicAdd(out + base + 16 + (2 * c + sp) * 3 + i,
                  S0F * oB[slot][sp][i]);
  }
}

extern "C" void kernel_launch(void* const* d_in, const int* in_sizes, int n_in,
                              void* d_out, int out_size) {
  const float* node_input = (const float*)d_in[0];
  const int*   edge_src   = (const int*)d_in[1];
  const int*   edge_dst   = (const int*)d_in[2];
  const float* edge_attr  = (const float*)d_in[3];
  const float* dist       = (const float*)d_in[4];
  const float* W1         = (const float*)d_in[5];
  const float* W2         = (const float*)d_in[6];
  float* out = (float*)d_out;

  cudaMemsetAsync(out, 0, (size_t)out_size * sizeof(float));
  prep_frags<<<80, 128>>>(W1, W2);
  fused_conv<<<NBLK, 128, SMEM_BYTES>>>(node_input, edge_src, edge_dst,
                                        edge_attr, dist, out);
}